// round 9
// baseline (speedup 1.0000x reference)
#include <cuda_runtime.h>

// LSTM T=4096, B=2048, I=2, H=4, L=4. Gate order i,f,g,o.
// lane = b*16 + l*4 + j; each thread additionally carries CH=4 independent
// batch chains in registers (weights shared) -> 8 batches/warp, 256 warps.
// The 4 chains interleave in the instruction stream and fill each other's
// dependency stalls (per-warp body latency is the established bottleneck).
// All sigmoids via 0.5*tanh(x/2)+0.5 (weights pre-scaled 0.5); g/cell tanh
// via tanh.approx. Skewed wavefront: body(s) runs layer l at step s-l.

#define TT 4096
#define BB 2048
#define CH 4

__device__ __forceinline__ float tanhx(float x) {
    float y; asm("tanh.approx.f32 %0, %1;" : "=f"(y) : "f"(x)); return y;
}

__global__ __launch_bounds__(32) void lstm_kernel(
    const float* __restrict__ x,     // (T, B, 2)
    const float* __restrict__ h0g,   // (L, B, 4)
    const float* __restrict__ c0g,   // (L, B, 4)
    const float* __restrict__ Wih0,  // (16, 2)
    const float* __restrict__ Wr,    // (3, 16, 4)  W_ih layers 1..3
    const float* __restrict__ Whh,   // (4, 16, 4)
    const float* __restrict__ bih,   // (4, 16)
    const float* __restrict__ bhh,   // (4, 16)
    float* __restrict__ out)         // ys (T,B,4) ++ hT (L,B,4) ++ cT (L,B,4)
{
    const int lane   = threadIdx.x & 31;
    const int b      = lane >> 4;             // SIMD batch sub-index 0..1
    const int l      = (lane >> 2) & 3;       // layer 0..3
    const int j      = lane & 3;              // hidden unit 0..3
    const int batch0 = blockIdx.x * (2 * CH) + b * CH;   // chains: batch0+ch

    // handoff source lanes (previous layer's quad)
    const int ps0 = lane - 4;
    const int ps1 = (lane - 4) ^ 1;
    const int ps2 = (lane - 4) ^ 2;
    const int ps3 = (lane - 4) ^ 3;

    // ---- weights: 4 gate rows of unit j in layer l (shared by all chains) ----
    // pre-scale: sigmoid gates (i,f,o) -> 0.5 (sigmoid via tanh), g -> 1.
    float win[4][4], wh[4][4], bz[4];
#pragma unroll
    for (int g4 = 0; g4 < 4; g4++) {
        const int   row = g4 * 4 + j;         // i_j, f_j, g_j, o_j
        const float sc  = (g4 == 2) ? 1.0f : 0.5f;
        if (l == 0) {
            win[g4][0] = Wih0[row * 2 + 0] * sc;
            win[g4][1] = Wih0[row * 2 + 1] * sc;
            win[g4][2] = 0.f; win[g4][3] = 0.f;
        } else {
#pragma unroll
            for (int m = 0; m < 4; m++)
                win[g4][m] = Wr[((l - 1) * 16 + row) * 4 + (j ^ m)] * sc;
        }
#pragma unroll
        for (int m = 0; m < 4; m++)
            wh[g4][m] = Whh[(l * 16 + row) * 4 + (j ^ m)] * sc;
        bz[g4] = (bih[l * 16 + row] + bhh[l * 16 + row]) * sc;
    }

    // ---- per-chain states ----
    float hown[CH][4], hin[CH][4], c[CH];
#pragma unroll
    for (int ch = 0; ch < CH; ch++) {
        const int bt = batch0 + ch;
#pragma unroll
        for (int m = 0; m < 4; m++) {
            hown[ch][m] = h0g[(l * BB + bt) * 4 + (j ^ m)];
            hin[ch][m]  = 0.f;
        }
        c[ch] = c0g[(l * BB + bt) * 4 + j];
    }

    float* __restrict__ ys  = out;
    float* __restrict__ hso = out + (size_t)TT * BB * 4;
    float* __restrict__ cso = hso + (size_t)4 * BB * 4;

    float4* __restrict__ ysp = reinterpret_cast<float4*>(ys) + batch0 - 3 * BB;

    // ---- x streams (prefetch depth 2) ----
    const float* xb = x + batch0 * 2;
    float2 xa[CH], xn[CH];
#pragma unroll
    for (int ch = 0; ch < CH; ch++) {
        xa[ch] = *reinterpret_cast<const float2*>(xb + ch * 2);
        xn[ch] = *reinterpret_cast<const float2*>(xb + ch * 2 + (size_t)BB * 2);
        if (l == 0) { hin[ch][0] = xa[ch].x; hin[ch][1] = xa[ch].y; }
    }

    auto body = [&](int s, bool masked) {
        int tp = s + 2; if (tp > TT - 1) tp = TT - 1;
        float2 xf[CH];
#pragma unroll
        for (int ch = 0; ch < CH; ch++)
            xf[ch] = *reinterpret_cast<const float2*>(
                         xb + ch * 2 + (size_t)tp * BB * 2);

        bool act  = masked ? ((unsigned)(s - l)     < (unsigned)TT) : true;
        bool actp = masked ? ((unsigned)(s + 1 - l) < (unsigned)TT) : true;

        float h[CH], h1[CH], h2[CH], h3[CH];
        float p0[CH], p1[CH], p2[CH], p3[CH];

#pragma unroll
        for (int ch = 0; ch < CH; ch++) {
            // ---- four gate pre-activations (two depth-4 chains each) ----
            float z[4];
#pragma unroll
            for (int g4 = 0; g4 < 4; g4++) {
                float u = fmaf(win[g4][0], hin[ch][0],
                          fmaf(win[g4][1], hin[ch][1], bz[g4]));
                u = fmaf(win[g4][2], hin[ch][2], u);
                u = fmaf(win[g4][3], hin[ch][3], u);
                float v = fmaf(wh[g4][0], hown[ch][0], wh[g4][1] * hown[ch][1]);
                v = fmaf(wh[g4][2], hown[ch][2], v);
                v = fmaf(wh[g4][3], hown[ch][3], v);
                z[g4] = u + v;
            }

            // ---- activations (all MUFU tanh) ----
            float si = fmaf(tanhx(z[0]), 0.5f, 0.5f);
            float sf = fmaf(tanhx(z[1]), 0.5f, 0.5f);
            float tg = tanhx(z[2]);
            float so = fmaf(tanhx(z[3]), 0.5f, 0.5f);

            float cn = fmaf(sf, c[ch], si * tg);
            float th = tanhx(cn);
            h[ch] = so * th;
            if (act) c[ch] = cn;

            // ---- 7 independent shuffles per chain ----
            h1[ch] = __shfl_xor_sync(0xffffffffu, h[ch], 1);
            h2[ch] = __shfl_xor_sync(0xffffffffu, h[ch], 2);
            h3[ch] = __shfl_xor_sync(0xffffffffu, h[ch], 3);
            p0[ch] = __shfl_sync(0xffffffffu, h[ch], ps0, 16);
            p1[ch] = __shfl_sync(0xffffffffu, h[ch], ps1, 16);
            p2[ch] = __shfl_sync(0xffffffffu, h[ch], ps2, 16);
            p3[ch] = __shfl_sync(0xffffffffu, h[ch], ps3, 16);
        }

#pragma unroll
        for (int ch = 0; ch < CH; ch++) {
            if (act) {
                hown[ch][0] = h[ch];  hown[ch][1] = h1[ch];
                hown[ch][2] = h2[ch]; hown[ch][3] = h3[ch];
                if (l == 3 && j == 0)
                    ysp[ch] = make_float4(h[ch], h1[ch], h2[ch], h3[ch]);
            }
            xa[ch] = xn[ch]; xn[ch] = xf[ch];
            if (l == 0) { hin[ch][0] = xa[ch].x; hin[ch][1] = xa[ch].y; }
            else if (actp) {
                hin[ch][0] = p0[ch]; hin[ch][1] = p1[ch];
                hin[ch][2] = p2[ch]; hin[ch][3] = p3[ch];
            }
        }
        ysp += BB;
    };

    body(0, true); body(1, true); body(2, true);
#pragma unroll 1
    for (int s = 3; s < TT; s++) body(s, false);
    body(TT, true); body(TT + 1, true); body(TT + 2, true);

    // ---- final hT / cT ----
#pragma unroll
    for (int ch = 0; ch < CH; ch++) {
        const int bt = batch0 + ch;
        if (j == 0)
            *reinterpret_cast<float4*>(hso + (l * BB + bt) * 4) =
                make_float4(hown[ch][0], hown[ch][1], hown[ch][2], hown[ch][3]);
        cso[(l * BB + bt) * 4 + j] = c[ch];
    }
}

extern "C" void kernel_launch(void* const* d_in, const int* in_sizes, int n_in,
                              void* d_out, int out_size) {
    (void)in_sizes; (void)n_in; (void)out_size;
    const float* x    = (const float*)d_in[0];
    const float* h0   = (const float*)d_in[1];
    const float* c0   = (const float*)d_in[2];
    const float* Wih0 = (const float*)d_in[3];
    const float* Wr   = (const float*)d_in[4];
    const float* Whh  = (const float*)d_in[5];
    const float* bih  = (const float*)d_in[6];
    const float* bhh  = (const float*)d_in[7];
    // 8 batches per warp (2 SIMD x 4 chains), 1 warp per block: 256 blocks
    lstm_kernel<<<BB / (2 * CH), 32>>>(x, h0, c0, Wih0, Wr, Whh, bih, bhh,
                                       (float*)d_out);
}

// round 10
// speedup vs baseline: 1.4935x; 1.4935x over previous
#include <cuda_runtime.h>

// LSTM T=4096, B=2048, I=2, H=4, L=4. Gate order i,f,g,o.
// lane = b*16 + l*4 + j : b = batch-in-warp (2), l = layer (4), j = unit (4).
// Each lane computes all 4 gate rows of its unit locally; cell update is
// thread-local. 7 shuffles/body, all independent, all sourced from h.
// Skewed wavefront: body(s) runs layer l at step s-l.
// ALL activations via tanh.approx (sigmoid = 0.5*tanh(x/2)+0.5, weights
// pre-scaled by 0.5). 4 warps per block so warps spread across all 4 SMSPs
// (wid%4 mapping) — single-warp blocks serialized on SMSP 0.

#define TT 4096
#define BB 2048

__device__ __forceinline__ float tanhx(float x) {
    float y; asm("tanh.approx.f32 %0, %1;" : "=f"(y) : "f"(x)); return y;
}

__global__ __launch_bounds__(128) void lstm_kernel(
    const float* __restrict__ x,     // (T, B, 2)
    const float* __restrict__ h0g,   // (L, B, 4)
    const float* __restrict__ c0g,   // (L, B, 4)
    const float* __restrict__ Wih0,  // (16, 2)
    const float* __restrict__ Wr,    // (3, 16, 4)  W_ih layers 1..3
    const float* __restrict__ Whh,   // (4, 16, 4)
    const float* __restrict__ bih,   // (4, 16)
    const float* __restrict__ bhh,   // (4, 16)
    float* __restrict__ out)         // ys (T,B,4) ++ hT (L,B,4) ++ cT (L,B,4)
{
    const int lane  = threadIdx.x & 31;
    const int warp  = threadIdx.x >> 5;
    const int b     = lane >> 4;              // batch sub-index in warp 0..1
    const int l     = (lane >> 2) & 3;        // layer 0..3
    const int j     = lane & 3;               // hidden unit 0..3
    const int batch = blockIdx.x * 8 + warp * 2 + b;

    // handoff source lanes (previous layer's quad)
    const int ps0 = lane - 4;
    const int ps1 = (lane - 4) ^ 1;
    const int ps2 = (lane - 4) ^ 2;
    const int ps3 = (lane - 4) ^ 3;

    // ---- weights: 4 gate rows of unit j in layer l ----
    // pre-scale: sigmoid gates (i,f,o) -> 0.5 (sigmoid via tanh), g -> 1.
    float win[4][4], wh[4][4], bz[4];
#pragma unroll
    for (int g4 = 0; g4 < 4; g4++) {
        const int   row = g4 * 4 + j;         // i_j, f_j, g_j, o_j
        const float sc  = (g4 == 2) ? 1.0f : 0.5f;
        if (l == 0) {
            win[g4][0] = Wih0[row * 2 + 0] * sc;
            win[g4][1] = Wih0[row * 2 + 1] * sc;
            win[g4][2] = 0.f; win[g4][3] = 0.f;
        } else {
#pragma unroll
            for (int m = 0; m < 4; m++)
                win[g4][m] = Wr[((l - 1) * 16 + row) * 4 + (j ^ m)] * sc;
        }
#pragma unroll
        for (int m = 0; m < 4; m++)
            wh[g4][m] = Whh[(l * 16 + row) * 4 + (j ^ m)] * sc;
        bz[g4] = (bih[l * 16 + row] + bhh[l * 16 + row]) * sc;
    }

    // ---- states ----
    float hown[4], hin[4], c;
#pragma unroll
    for (int m = 0; m < 4; m++) {
        hown[m] = h0g[(l * BB + batch) * 4 + (j ^ m)];
        hin[m]  = 0.f;
    }
    c = c0g[(l * BB + batch) * 4 + j];

    float* __restrict__ ys  = out;
    float* __restrict__ hso = out + (size_t)TT * BB * 4;
    float* __restrict__ cso = hso + (size_t)4 * BB * 4;

    float4* __restrict__ ysp = reinterpret_cast<float4*>(ys) + batch - 3 * BB;

    // ---- x stream (prefetch depth 3) ----
    const float* xb = x + batch * 2;
    float2 xa = *reinterpret_cast<const float2*>(xb);                       // x[0]
    float2 xn = *reinterpret_cast<const float2*>(xb + (size_t)1 * BB * 2);  // x[1]
    float2 xm = *reinterpret_cast<const float2*>(xb + (size_t)2 * BB * 2);  // x[2]
    if (l == 0) { hin[0] = xa.x; hin[1] = xa.y; }

    auto body = [&](int s, bool masked) {
        int tp = s + 3; if (tp > TT - 1) tp = TT - 1;
        float2 xf = *reinterpret_cast<const float2*>(xb + (size_t)tp * BB * 2);

        // ---- four gate pre-activations (two depth-4 chains each) ----
        float z[4];
#pragma unroll
        for (int g4 = 0; g4 < 4; g4++) {
            float u = fmaf(win[g4][0], hin[0],
                      fmaf(win[g4][1], hin[1], bz[g4]));
            u = fmaf(win[g4][2], hin[2], u);
            u = fmaf(win[g4][3], hin[3], u);
            float v = fmaf(wh[g4][0], hown[0], wh[g4][1] * hown[1]);
            v = fmaf(wh[g4][2], hown[2], v);
            v = fmaf(wh[g4][3], hown[3], v);
            z[g4] = u + v;
        }

        // ---- activations (all MUFU tanh) ----
        float si = fmaf(tanhx(z[0]), 0.5f, 0.5f);   // sigma(i)
        float sf = fmaf(tanhx(z[1]), 0.5f, 0.5f);   // sigma(f)
        float tg = tanhx(z[2]);                     // tanh(g)
        float so = fmaf(tanhx(z[3]), 0.5f, 0.5f);   // sigma(o)

        float cn = fmaf(sf, c, si * tg);
        float th = tanhx(cn);                       // tanh(c)
        float h  = so * th;

        // ---- 7 independent shuffles, all sourced from h ----
        float h1 = __shfl_xor_sync(0xffffffffu, h, 1);
        float h2 = __shfl_xor_sync(0xffffffffu, h, 2);
        float h3 = __shfl_xor_sync(0xffffffffu, h, 3);
        float p0 = __shfl_sync(0xffffffffu, h, ps0, 16);
        float p1 = __shfl_sync(0xffffffffu, h, ps1, 16);
        float p2 = __shfl_sync(0xffffffffu, h, ps2, 16);
        float p3 = __shfl_sync(0xffffffffu, h, ps3, 16);

        bool act  = masked ? ((unsigned)(s - l)     < (unsigned)TT) : true;
        bool actp = masked ? ((unsigned)(s + 1 - l) < (unsigned)TT) : true;

        if (act) {
            c = cn;
            hown[0] = h;  hown[1] = h1; hown[2] = h2; hown[3] = h3;
            if (l == 3 && j == 0)
                *ysp = make_float4(h, h1, h2, h3);
        }
        ysp += BB;

        xa = xn; xn = xm; xm = xf;
        if (l == 0) { hin[0] = xa.x; hin[1] = xa.y; }
        else if (actp) { hin[0] = p0; hin[1] = p1; hin[2] = p2; hin[3] = p3; }
    };

    body(0, true); body(1, true); body(2, true);
#pragma unroll 2
    for (int s = 3; s < TT; s++) body(s, false);
    body(TT, true); body(TT + 1, true); body(TT + 2, true);

    // ---- final hT / cT ----
    if (j == 0)   // hown[m] = h_m natural order for j==0
        *reinterpret_cast<float4*>(hso + (l * BB + batch) * 4) =
            make_float4(hown[0], hown[1], hown[2], hown[3]);
    cso[(l * BB + batch) * 4 + j] = c;
}

extern "C" void kernel_launch(void* const* d_in, const int* in_sizes, int n_in,
                              void* d_out, int out_size) {
    (void)in_sizes; (void)n_in; (void)out_size;
    const float* x    = (const float*)d_in[0];
    const float* h0   = (const float*)d_in[1];
    const float* c0   = (const float*)d_in[2];
    const float* Wih0 = (const float*)d_in[3];
    const float* Wr   = (const float*)d_in[4];
    const float* Whh  = (const float*)d_in[5];
    const float* bih  = (const float*)d_in[6];
    const float* bhh  = (const float*)d_in[7];
    // 8 batches per block (4 warps x 2), 256 blocks -> 1024 warps spread
    // across all 4 SMSPs per SM.
    lstm_kernel<<<BB / 8, 128>>>(x, h0, c0, Wih0, Wr, Whh, bih, bhh,
                                 (float*)d_out);
}